// round 12
// baseline (speedup 1.0000x reference)
#include <cuda_runtime.h>
#include <cuda_fp16.h>
#include <cstdint>

#define MAX_NODES 100000
#define MAX_EDGES 3200000
#define HID 64
#define CAP 128          // padded-CSR capacity per node (Poisson(32); max deg ~60)
#define MAX_SPILL 4096   // overflow list (expected empty)

// Scratch (__device__ globals; 16B aligned)
__device__ __align__(16) int    g_cnt[MAX_NODES];
__device__ __align__(16) int    g_srcs[MAX_NODES * CAP];  // padded CSR
__device__                int   g_nspill;
__device__ __align__(16) int    g_spill_d[MAX_SPILL];
__device__ __align__(16) int    g_spill_s[MAX_SPILL];
__device__ __align__(16) float  g_dinv[MAX_NODES];
__device__ __align__(16) __half g_h1[MAX_NODES * HID];   // h1' = (x@W1)*dinv, fp16
__device__ __align__(16) __half g_h2[MAX_NODES * HID];   // h2' = (hid@W2)*dinv, fp16

// ---------------------------------------------------------------------------
// CSR construction (single pass, padded)
// ---------------------------------------------------------------------------
__global__ void zero_cnt_kernel(int* cnt, int* nspill, int N) {
    int i = blockIdx.x * blockDim.x + threadIdx.x;
    if (i < N) cnt[i] = 0;
    if (i == 0) *nspill = 0;
}

__global__ void hist_scatter_kernel(const int* __restrict__ src, const int* __restrict__ dst,
                                    int* cnt, int* __restrict__ srcs,
                                    int* nspill, int* spill_d, int* spill_s, int E) {
    int i = blockIdx.x * blockDim.x + threadIdx.x;
    if (i >= E) return;
    int s = src[i];
    int d = dst[i];
    int r = atomicAdd(&cnt[d], 1);
    if (r < CAP) {
        srcs[d * CAP + r] = s;
    } else {
        int k = atomicAdd(nspill, 1);
        if (k < MAX_SPILL) { spill_d[k] = d; spill_s[k] = s; }
    }
}

__global__ void dinv_kernel(const int* __restrict__ cnt, float* dinv, int N) {
    int i = blockIdx.x * blockDim.x + threadIdx.x;
    if (i < N) dinv[i] = rsqrtf((float)cnt[i] + 1.0f);  // +1 self-loop
}

// ---------------------------------------------------------------------------
// tf32 helpers
// ---------------------------------------------------------------------------
__device__ __forceinline__ unsigned f2tf32(float f) {
    unsigned u;
    asm("cvt.rna.tf32.f32 %0, %1;" : "=r"(u) : "f"(f));
    return u;
}

__device__ __forceinline__ void mma_tf32(float* c, const unsigned* a, const unsigned* b) {
    asm volatile(
        "mma.sync.aligned.m16n8k8.row.col.f32.tf32.tf32.f32 "
        "{%0,%1,%2,%3}, {%4,%5,%6,%7}, {%8,%9}, {%0,%1,%2,%3};"
        : "+f"(c[0]), "+f"(c[1]), "+f"(c[2]), "+f"(c[3])
        : "r"(a[0]), "r"(a[1]), "r"(a[2]), "r"(a[3]), "r"(b[0]), "r"(b[1]));
}

// ---------------------------------------------------------------------------
// GEMM1 (tf32, cp.async double-buffered): h1 = half( (x @ W1) * dinv[r] )
// BM=128, BN=64, BK=32; 8 warps.
// ---------------------------------------------------------------------------
#define ASTR 36
#define BSTR 72
#define ATILE (128 * ASTR)
#define BTILE (32 * BSTR)
#define GEMM_SMEM_BYTES (2 * (ATILE + BTILE) * 4)

template <int K>
__launch_bounds__(256)
__global__ void gemm_tf32_kernel(const float* __restrict__ A, const float* __restrict__ Bm,
                                 const float* __restrict__ dinv, __half* __restrict__ C,
                                 int M) {
    extern __shared__ float smem[];
    float* As = smem;
    float* Bs = smem + 2 * ATILE;

    constexpr int T = K / 32;
    const int tid = threadIdx.x;
    const int lane = tid & 31;
    const int warp = tid >> 5;
    const int wm = (warp & 3) * 32;
    const int wn = (warp >> 2) * 32;
    const int block_row = blockIdx.x * 128;
    const int g = lane >> 2;
    const int tg = lane & 3;

    float acc[2][4][4];
#pragma unroll
    for (int mi = 0; mi < 2; mi++)
#pragma unroll
        for (int na = 0; na < 4; na++)
#pragma unroll
            for (int r = 0; r < 4; r++) acc[mi][na][r] = 0.f;

    auto prefetch = [&](int t, int buf) {
        int k0 = t * 32;
#pragma unroll
        for (int i = 0; i < 4; i++) {
            int idx = tid + i * 256;
            int r = idx >> 3;
            int c4 = (idx & 7) * 4;
            int grow = block_row + r;
            const float* sp = A + (size_t)(grow < M ? grow : 0) * K + k0 + c4;
            unsigned ds = (unsigned)__cvta_generic_to_shared(As + buf * ATILE + r * ASTR + c4);
            int sz = (grow < M) ? 16 : 0;
            asm volatile("cp.async.cg.shared.global [%0], [%1], 16, %2;"
                         :: "r"(ds), "l"(sp), "r"(sz));
        }
#pragma unroll
        for (int i = 0; i < 2; i++) {
            int idx = tid + i * 256;
            int r = idx >> 4;
            int c4 = (idx & 15) * 4;
            const float* sp = Bm + (size_t)(k0 + r) * 64 + c4;
            unsigned ds = (unsigned)__cvta_generic_to_shared(Bs + buf * BTILE + r * BSTR + c4);
            asm volatile("cp.async.cg.shared.global [%0], [%1], 16;" :: "r"(ds), "l"(sp));
        }
        asm volatile("cp.async.commit_group;");
    };

    prefetch(0, 0);

    for (int t = 0; t < T; t++) {
        if (t + 1 < T) {
            prefetch(t + 1, (t + 1) & 1);
            asm volatile("cp.async.wait_group 1;");
        } else {
            asm volatile("cp.async.wait_group 0;");
        }
        __syncthreads();

        const float* At = As + (t & 1) * ATILE;
        const float* Bt = Bs + (t & 1) * BTILE;

#pragma unroll
        for (int ks = 0; ks < 4; ks++) {
            const int kb = ks * 8;
            unsigned a[2][4], b[4][2];
#pragma unroll
            for (int mi = 0; mi < 2; mi++) {
                int row = wm + mi * 16 + g;
                a[mi][0] = f2tf32(At[row * ASTR + kb + tg]);
                a[mi][1] = f2tf32(At[(row + 8) * ASTR + kb + tg]);
                a[mi][2] = f2tf32(At[row * ASTR + kb + tg + 4]);
                a[mi][3] = f2tf32(At[(row + 8) * ASTR + kb + tg + 4]);
            }
#pragma unroll
            for (int na = 0; na < 4; na++) {
                int col = wn + na * 8 + g;
                b[na][0] = f2tf32(Bt[(kb + tg) * BSTR + col]);
                b[na][1] = f2tf32(Bt[(kb + tg + 4) * BSTR + col]);
            }
#pragma unroll
            for (int mi = 0; mi < 2; mi++)
#pragma unroll
                for (int na = 0; na < 4; na++) mma_tf32(acc[mi][na], a[mi], b[na]);
        }
        __syncthreads();
    }

#pragma unroll
    for (int mi = 0; mi < 2; mi++) {
        int row_lo = block_row + wm + mi * 16 + g;
        int row_hi = row_lo + 8;
        float s_lo = (row_lo < M) ? dinv[row_lo] : 0.f;
        float s_hi = (row_hi < M) ? dinv[row_hi] : 0.f;
#pragma unroll
        for (int na = 0; na < 4; na++) {
            int col = wn + na * 8 + 2 * tg;
            if (row_lo < M) {
                __half2 h = __floats2half2_rn(acc[mi][na][0] * s_lo, acc[mi][na][1] * s_lo);
                *reinterpret_cast<__half2*>(&C[(size_t)row_lo * 64 + col]) = h;
            }
            if (row_hi < M) {
                __half2 h = __floats2half2_rn(acc[mi][na][2] * s_hi, acc[mi][na][3] * s_hi);
                *reinterpret_cast<__half2*>(&C[(size_t)row_hi * 64 + col]) = h;
            }
        }
    }
}

// ---------------------------------------------------------------------------
// fp16 accumulate helper
// ---------------------------------------------------------------------------
__device__ __forceinline__ void acc_half4(float4& acc, uint2 u) {
    __half2 h0 = *reinterpret_cast<const __half2*>(&u.x);
    __half2 h1 = *reinterpret_cast<const __half2*>(&u.y);
    float2 f0 = __half22float2(h0);
    float2 f1 = __half22float2(h1);
    acc.x += f0.x; acc.y += f0.y; acc.z += f1.x; acc.w += f1.y;
}

// ---------------------------------------------------------------------------
// FUSED gather1 + GEMM2:
//   hid[16 nodes][64] = relu(dinv*(h1'[d] + sum h1'[src]) + b1)  (smem only)
//   h2[node,:] = half( (hid @ W2)[node,:] * dinv[node] )
// 256 threads = 16 nodes/block; W2 prefetched via cp.async during gather.
// ---------------------------------------------------------------------------
#define HSTR 68   // hid smem stride (68%32==4 -> bank 4g+tg, conflict-free)
#define WSTR 72   // W2 smem stride  (72%32==8 -> bank 8tg+g, conflict-free)
#define GA_SMEM_BYTES ((16 * HSTR + 64 * WSTR) * 4)

__launch_bounds__(256)
__global__ void gather_gemm2_kernel(const uint2* __restrict__ hs, const int* __restrict__ cnt,
                                    const int* __restrict__ srcs, const float* __restrict__ dinv,
                                    const float* __restrict__ b1, const float* __restrict__ W2,
                                    const int* __restrict__ nspill, const int* __restrict__ spill_d,
                                    const int* __restrict__ spill_s,
                                    __half* __restrict__ h2, int N) {
    extern __shared__ float sm[];
    float* hid_s = sm;               // [16][HSTR]
    float* w2_s = sm + 16 * HSTR;    // [64][WSTR]

    const int tid = threadIdx.x;
    const int base = blockIdx.x * 16;

    // prefetch W2 (64x64 fp32) into smem: 1024 float4, 4 per thread
#pragma unroll
    for (int i = 0; i < 4; i++) {
        int idx = tid + i * 256;
        int r = idx >> 4;
        int c4 = (idx & 15) * 4;
        const float* sp = W2 + (size_t)r * 64 + c4;
        unsigned ds = (unsigned)__cvta_generic_to_shared(w2_s + r * WSTR + c4);
        asm volatile("cp.async.cg.shared.global [%0], [%1], 16;" :: "r"(ds), "l"(sp));
    }
    asm volatile("cp.async.commit_group;");

    // ---- gather phase: 16 threads per node ----
    {
        int node = base + (tid >> 4);
        int lane = tid & 15;
        float4 acc = make_float4(0.f, 0.f, 0.f, 0.f);
        if (node < N) {
            acc_half4(acc, hs[(size_t)node * 16 + lane]);  // self-loop
            const int c = cnt[node];
            int e = node * CAP;
            const int end = e + min(c, CAP);
            for (; e + 4 <= end; e += 4) {
                int s0 = srcs[e], s1 = srcs[e + 1], s2 = srcs[e + 2], s3 = srcs[e + 3];
                uint2 v0 = hs[(size_t)s0 * 16 + lane];
                uint2 v1 = hs[(size_t)s1 * 16 + lane];
                uint2 v2 = hs[(size_t)s2 * 16 + lane];
                uint2 v3 = hs[(size_t)s3 * 16 + lane];
                acc_half4(acc, v0); acc_half4(acc, v1);
                acc_half4(acc, v2); acc_half4(acc, v3);
            }
            for (; e < end; e++) acc_half4(acc, hs[(size_t)srcs[e] * 16 + lane]);
            if (c > CAP) {  // overflow fixup (empty in practice)
                int ns = min(*nspill, MAX_SPILL);
                for (int j = 0; j < ns; j++)
                    if (spill_d[j] == node) acc_half4(acc, hs[(size_t)spill_s[j] * 16 + lane]);
            }
            float dd = dinv[node];
            float4 bv = reinterpret_cast<const float4*>(b1)[lane];
            acc.x = fmaxf(fmaf(acc.x, dd, bv.x), 0.f);
            acc.y = fmaxf(fmaf(acc.y, dd, bv.y), 0.f);
            acc.z = fmaxf(fmaf(acc.z, dd, bv.z), 0.f);
            acc.w = fmaxf(fmaf(acc.w, dd, bv.w), 0.f);
        }
        // store hid row to smem (pre-converted to tf32 to skip cvt in mma phase)
        int r = tid >> 4;
        float* hp = hid_s + r * HSTR + (tid & 15) * 4;
        hp[0] = acc.x; hp[1] = acc.y; hp[2] = acc.z; hp[3] = acc.w;
    }

    asm volatile("cp.async.wait_group 0;");
    __syncthreads();

    // ---- GEMM2 phase: C[16,64] = hid_s[16,64] @ W2[64,64]; warp w -> cols [8w,8w+8) ----
    {
        const int lane = tid & 31;
        const int warp = tid >> 5;
        const int g = lane >> 2;
        const int tg = lane & 3;
        const int col = warp * 8 + g;

        float c[4] = {0.f, 0.f, 0.f, 0.f};
#pragma unroll
        for (int ks = 0; ks < 8; ks++) {
            const int kb = ks * 8;
            unsigned a[4], b[2];
            a[0] = f2tf32(hid_s[g * HSTR + kb + tg]);
            a[1] = f2tf32(hid_s[(g + 8) * HSTR + kb + tg]);
            a[2] = f2tf32(hid_s[g * HSTR + kb + tg + 4]);
            a[3] = f2tf32(hid_s[(g + 8) * HSTR + kb + tg + 4]);
            b[0] = f2tf32(w2_s[(kb + tg) * WSTR + col]);
            b[1] = f2tf32(w2_s[(kb + tg + 4) * WSTR + col]);
            mma_tf32(c, a, b);
        }

        int row_lo = base + g;
        int row_hi = base + g + 8;
        int ocol = warp * 8 + 2 * tg;
        if (row_lo < N) {
            float s = dinv[row_lo];
            __half2 h = __floats2half2_rn(c[0] * s, c[1] * s);
            *reinterpret_cast<__half2*>(&h2[(size_t)row_lo * 64 + ocol]) = h;
        }
        if (row_hi < N) {
            float s = dinv[row_hi];
            __half2 h = __floats2half2_rn(c[2] * s, c[3] * s);
            *reinterpret_cast<__half2*>(&h2[(size_t)row_hi * 64 + ocol]) = h;
        }
    }
}

// ---------------------------------------------------------------------------
// Final gather: out[d] = dinv[d]*(h2'[d] + sum h2'[src]) + b2   (fp32 out)
// ---------------------------------------------------------------------------
__global__ void gather_kernel(const uint2* __restrict__ hs, const int* __restrict__ cnt,
                              const int* __restrict__ srcs, const float* __restrict__ dinv,
                              const float* __restrict__ bias,
                              const int* __restrict__ nspill, const int* __restrict__ spill_d,
                              const int* __restrict__ spill_s,
                              float4* __restrict__ out, int N) {
    int i = blockIdx.x * blockDim.x + threadIdx.x;
    if (i >= N * 16) return;
    int node = i >> 4;
    int lane = i & 15;

    float4 acc = make_float4(0.f, 0.f, 0.f, 0.f);
    acc_half4(acc, hs[(size_t)node * 16 + lane]);
    const int c = cnt[node];
    int e = node * CAP;
    const int end = e + min(c, CAP);

    for (; e + 4 <= end; e += 4) {
        int s0 = srcs[e], s1 = srcs[e + 1], s2 = srcs[e + 2], s3 = srcs[e + 3];
        uint2 v0 = hs[(size_t)s0 * 16 + lane];
        uint2 v1 = hs[(size_t)s1 * 16 + lane];
        uint2 v2 = hs[(size_t)s2 * 16 + lane];
        uint2 v3 = hs[(size_t)s3 * 16 + lane];
        acc_half4(acc, v0); acc_half4(acc, v1);
        acc_half4(acc, v2); acc_half4(acc, v3);
    }
    for (; e < end; e++) acc_half4(acc, hs[(size_t)srcs[e] * 16 + lane]);

    if (c > CAP) {
        int ns = min(*nspill, MAX_SPILL);
        for (int j = 0; j < ns; j++)
            if (spill_d[j] == node) acc_half4(acc, hs[(size_t)spill_s[j] * 16 + lane]);
    }

    float dd = dinv[node];
    float4 bv = reinterpret_cast<const float4*>(bias)[lane];
    out[(size_t)node * 16 + lane] = make_float4(
        fmaf(acc.x, dd, bv.x), fmaf(acc.y, dd, bv.y),
        fmaf(acc.z, dd, bv.z), fmaf(acc.w, dd, bv.w));
}

// ---------------------------------------------------------------------------
// launch
// ---------------------------------------------------------------------------
extern "C" void kernel_launch(void* const* d_in, const int* in_sizes, int n_in,
                              void* d_out, int out_size) {
    const float* x = (const float*)d_in[0];
    const int* edge_index = (const int*)d_in[1];
    const float* W1 = (const float*)d_in[2];
    const float* b1 = (const float*)d_in[3];
    const float* W2 = (const float*)d_in[4];
    const float* b2 = (const float*)d_in[5];
    float* out = (float*)d_out;

    const int IN_CH = 256;
    const int N = in_sizes[0] / IN_CH;  // 100000
    const int E = in_sizes[1] / 2;      // 3200000
    const int* src = edge_index;
    const int* dst = edge_index + E;

    int *cnt, *srcs, *nspill, *spill_d, *spill_s;
    float *dinv;
    __half *h1, *h2;
    cudaGetSymbolAddress((void**)&cnt, g_cnt);
    cudaGetSymbolAddress((void**)&srcs, g_srcs);
    cudaGetSymbolAddress((void**)&nspill, g_nspill);
    cudaGetSymbolAddress((void**)&spill_d, g_spill_d);
    cudaGetSymbolAddress((void**)&spill_s, g_spill_s);
    cudaGetSymbolAddress((void**)&dinv, g_dinv);
    cudaGetSymbolAddress((void**)&h1, g_h1);
    cudaGetSymbolAddress((void**)&h2, g_h2);

    static bool attr_done = false;
    if (!attr_done) {
        cudaFuncSetAttribute(gemm_tf32_kernel<256>,
                             cudaFuncAttributeMaxDynamicSharedMemorySize, GEMM_SMEM_BYTES);
        cudaFuncSetAttribute(gather_gemm2_kernel,
                             cudaFuncAttributeMaxDynamicSharedMemorySize, GA_SMEM_BYTES);
        attr_done = true;
    }

    const int T = 256;
    int nBlkN = (N + T - 1) / T;
    int nBlkE = (E + T - 1) / T;
    int nBlkG = (N + 127) / 128;
    int nBlkF = (N + 15) / 16;             // fused gather+gemm2 blocks
    int nBlkGa = (N * 16 + T - 1) / T;

    // padded CSR build (single pass)
    zero_cnt_kernel<<<nBlkN, T>>>(cnt, nspill, N);
    hist_scatter_kernel<<<nBlkE, T>>>(src, dst, cnt, srcs, nspill, spill_d, spill_s, E);
    dinv_kernel<<<nBlkN, T>>>(cnt, dinv, N);

    // layer 1 GEMM
    gemm_tf32_kernel<256><<<nBlkG, T, GEMM_SMEM_BYTES>>>(x, W1, dinv, h1, N);

    // fused: gather1 (+b1, relu) + GEMM2 (+dinv scale, fp16 h2)
    gather_gemm2_kernel<<<nBlkF, T, GA_SMEM_BYTES>>>(
        (const uint2*)h1, cnt, srcs, dinv, b1, W2,
        nspill, spill_d, spill_s, h2, N);

    // final gather (+b2), fp32 out
    gather_kernel<<<nBlkGa, T>>>((const uint2*)h2, cnt, srcs, dinv, b2,
                                 nspill, spill_d, spill_s, (float4*)out, N);
}

// round 13
// speedup vs baseline: 1.4665x; 1.4665x over previous
#include <cuda_runtime.h>
#include <cuda_fp16.h>
#include <cstdint>

#define MAX_NODES 100000
#define MAX_EDGES 3200000
#define HID 64
#define CAP 128          // padded-CSR capacity per node (Poisson(32); max deg ~60)
#define MAX_SPILL 4096   // overflow list (expected empty)

// Scratch (__device__ globals; 16B aligned)
__device__ __align__(16) int    g_cnt[MAX_NODES];
__device__ __align__(16) int    g_srcs[MAX_NODES * CAP];  // padded CSR
__device__                int   g_nspill;
__device__ __align__(16) int    g_spill_d[MAX_SPILL];
__device__ __align__(16) int    g_spill_s[MAX_SPILL];
__device__ __align__(16) float  g_dinv[MAX_NODES];
__device__ __align__(16) __half g_h1[MAX_NODES * HID];   // x@W1 (raw, then *dinv in place)
__device__ __align__(16) float  g_hid[MAX_NODES * HID];  // relu'd hidden (fp32)
__device__ __align__(16) __half g_h2[MAX_NODES * HID];   // h2' = (hid@W2)*dinv, fp16

// ---------------------------------------------------------------------------
// CSR construction (single pass, padded)
// ---------------------------------------------------------------------------
__global__ void zero_cnt_kernel(int* cnt, int* nspill, int N) {
    int i = blockIdx.x * blockDim.x + threadIdx.x;
    if (i < N) cnt[i] = 0;
    if (i == 0) *nspill = 0;
}

__global__ void hist_scatter_kernel(const int* __restrict__ src, const int* __restrict__ dst,
                                    int* cnt, int* __restrict__ srcs,
                                    int* nspill, int* spill_d, int* spill_s, int E) {
    int i = blockIdx.x * blockDim.x + threadIdx.x;
    if (i >= E) return;
    int s = src[i];
    int d = dst[i];
    int r = atomicAdd(&cnt[d], 1);
    if (r < CAP) {
        srcs[d * CAP + r] = s;
    } else {
        int k = atomicAdd(nspill, 1);
        if (k < MAX_SPILL) { spill_d[k] = d; spill_s[k] = s; }
    }
}

__global__ void dinv_kernel(const int* __restrict__ cnt, float* dinv, int N) {
    int i = blockIdx.x * blockDim.x + threadIdx.x;
    if (i < N) dinv[i] = rsqrtf((float)cnt[i] + 1.0f);  // +1 self-loop
}

// h1[i] *= dinv[node]  (fp16 in place, uint2 = 4 halves per thread)
__global__ void scale_h1_kernel(uint2* __restrict__ h1, const float* __restrict__ dinv, int N) {
    int i = blockIdx.x * blockDim.x + threadIdx.x;
    if (i >= N * 16) return;
    float dd = dinv[i >> 4];
    uint2 u = h1[i];
    __half2 a = *reinterpret_cast<__half2*>(&u.x);
    __half2 b = *reinterpret_cast<__half2*>(&u.y);
    float2 fa = __half22float2(a);
    float2 fb = __half22float2(b);
    __half2 ra = __floats2half2_rn(fa.x * dd, fa.y * dd);
    __half2 rb = __floats2half2_rn(fb.x * dd, fb.y * dd);
    u.x = *reinterpret_cast<unsigned*>(&ra);
    u.y = *reinterpret_cast<unsigned*>(&rb);
    h1[i] = u;
}

// ---------------------------------------------------------------------------
// tf32 helpers
// ---------------------------------------------------------------------------
__device__ __forceinline__ unsigned f2tf32(float f) {
    unsigned u;
    asm("cvt.rna.tf32.f32 %0, %1;" : "=r"(u) : "f"(f));
    return u;
}

__device__ __forceinline__ void mma_tf32(float* c, const unsigned* a, const unsigned* b) {
    asm volatile(
        "mma.sync.aligned.m16n8k8.row.col.f32.tf32.tf32.f32 "
        "{%0,%1,%2,%3}, {%4,%5,%6,%7}, {%8,%9}, {%0,%1,%2,%3};"
        : "+f"(c[0]), "+f"(c[1]), "+f"(c[2]), "+f"(c[3])
        : "r"(a[0]), "r"(a[1]), "r"(a[2]), "r"(a[3]), "r"(b[0]), "r"(b[1]));
}

// ---------------------------------------------------------------------------
// tf32 GEMM, cp.async double-buffered: C = half( (A @ B) [* dinv[r] if SCALE] )
// BM=128, BN=64, BK=32; 8 warps.
// ---------------------------------------------------------------------------
#define ASTR 36
#define BSTR 72
#define ATILE (128 * ASTR)
#define BTILE (32 * BSTR)
#define GEMM_SMEM_BYTES (2 * (ATILE + BTILE) * 4)

template <int K, bool SCALE>
__launch_bounds__(256)
__global__ void gemm_tf32_kernel(const float* __restrict__ A, const float* __restrict__ Bm,
                                 const float* __restrict__ dinv, __half* __restrict__ C,
                                 int M) {
    extern __shared__ float smem[];
    float* As = smem;
    float* Bs = smem + 2 * ATILE;

    constexpr int T = K / 32;
    const int tid = threadIdx.x;
    const int lane = tid & 31;
    const int warp = tid >> 5;
    const int wm = (warp & 3) * 32;
    const int wn = (warp >> 2) * 32;
    const int block_row = blockIdx.x * 128;
    const int g = lane >> 2;
    const int tg = lane & 3;

    float acc[2][4][4];
#pragma unroll
    for (int mi = 0; mi < 2; mi++)
#pragma unroll
        for (int na = 0; na < 4; na++)
#pragma unroll
            for (int r = 0; r < 4; r++) acc[mi][na][r] = 0.f;

    auto prefetch = [&](int t, int buf) {
        int k0 = t * 32;
#pragma unroll
        for (int i = 0; i < 4; i++) {
            int idx = tid + i * 256;
            int r = idx >> 3;
            int c4 = (idx & 7) * 4;
            int grow = block_row + r;
            const float* sp = A + (size_t)(grow < M ? grow : 0) * K + k0 + c4;
            unsigned ds = (unsigned)__cvta_generic_to_shared(As + buf * ATILE + r * ASTR + c4);
            int sz = (grow < M) ? 16 : 0;
            asm volatile("cp.async.cg.shared.global [%0], [%1], 16, %2;"
                         :: "r"(ds), "l"(sp), "r"(sz));
        }
#pragma unroll
        for (int i = 0; i < 2; i++) {
            int idx = tid + i * 256;
            int r = idx >> 4;
            int c4 = (idx & 15) * 4;
            const float* sp = Bm + (size_t)(k0 + r) * 64 + c4;
            unsigned ds = (unsigned)__cvta_generic_to_shared(Bs + buf * BTILE + r * BSTR + c4);
            asm volatile("cp.async.cg.shared.global [%0], [%1], 16;" :: "r"(ds), "l"(sp));
        }
        asm volatile("cp.async.commit_group;");
    };

    prefetch(0, 0);

    for (int t = 0; t < T; t++) {
        if (t + 1 < T) {
            prefetch(t + 1, (t + 1) & 1);
            asm volatile("cp.async.wait_group 1;");
        } else {
            asm volatile("cp.async.wait_group 0;");
        }
        __syncthreads();

        const float* At = As + (t & 1) * ATILE;
        const float* Bt = Bs + (t & 1) * BTILE;

#pragma unroll
        for (int ks = 0; ks < 4; ks++) {
            const int kb = ks * 8;
            unsigned a[2][4], b[4][2];
#pragma unroll
            for (int mi = 0; mi < 2; mi++) {
                int row = wm + mi * 16 + g;
                a[mi][0] = f2tf32(At[row * ASTR + kb + tg]);
                a[mi][1] = f2tf32(At[(row + 8) * ASTR + kb + tg]);
                a[mi][2] = f2tf32(At[row * ASTR + kb + tg + 4]);
                a[mi][3] = f2tf32(At[(row + 8) * ASTR + kb + tg + 4]);
            }
#pragma unroll
            for (int na = 0; na < 4; na++) {
                int col = wn + na * 8 + g;
                b[na][0] = f2tf32(Bt[(kb + tg) * BSTR + col]);
                b[na][1] = f2tf32(Bt[(kb + tg + 4) * BSTR + col]);
            }
#pragma unroll
            for (int mi = 0; mi < 2; mi++)
#pragma unroll
                for (int na = 0; na < 4; na++) mma_tf32(acc[mi][na], a[mi], b[na]);
        }
        __syncthreads();
    }

#pragma unroll
    for (int mi = 0; mi < 2; mi++) {
        int row_lo = block_row + wm + mi * 16 + g;
        int row_hi = row_lo + 8;
        float s_lo = 1.f, s_hi = 1.f;
        if (SCALE) {
            s_lo = (row_lo < M) ? dinv[row_lo] : 0.f;
            s_hi = (row_hi < M) ? dinv[row_hi] : 0.f;
        }
#pragma unroll
        for (int na = 0; na < 4; na++) {
            int col = wn + na * 8 + 2 * tg;
            if (row_lo < M) {
                __half2 h = __floats2half2_rn(acc[mi][na][0] * s_lo, acc[mi][na][1] * s_lo);
                *reinterpret_cast<__half2*>(&C[(size_t)row_lo * 64 + col]) = h;
            }
            if (row_hi < M) {
                __half2 h = __floats2half2_rn(acc[mi][na][2] * s_hi, acc[mi][na][3] * s_hi);
                *reinterpret_cast<__half2*>(&C[(size_t)row_hi * 64 + col]) = h;
            }
        }
    }
}

// ---------------------------------------------------------------------------
// Gather-reduce (fp16 table, padded CSR)
// ---------------------------------------------------------------------------
__device__ __forceinline__ void acc_half4(float4& acc, uint2 u) {
    __half2 h0 = *reinterpret_cast<const __half2*>(&u.x);
    __half2 h1 = *reinterpret_cast<const __half2*>(&u.y);
    float2 f0 = __half22float2(h0);
    float2 f1 = __half22float2(h1);
    acc.x += f0.x; acc.y += f0.y; acc.z += f1.x; acc.w += f1.y;
}

template <bool RELU>
__global__ void gather_kernel(const uint2* __restrict__ hs, const int* __restrict__ cnt,
                              const int* __restrict__ srcs, const float* __restrict__ dinv,
                              const float* __restrict__ bias,
                              const int* __restrict__ nspill, const int* __restrict__ spill_d,
                              const int* __restrict__ spill_s,
                              float4* __restrict__ out, int N) {
    int i = blockIdx.x * blockDim.x + threadIdx.x;
    if (i >= N * 16) return;
    int node = i >> 4;
    int lane = i & 15;

    float4 acc = make_float4(0.f, 0.f, 0.f, 0.f);
    acc_half4(acc, hs[(size_t)node * 16 + lane]);  // self-loop term
    const int c = cnt[node];
    int e = node * CAP;
    const int end = e + min(c, CAP);

    for (; e + 4 <= end; e += 4) {
        int s0 = srcs[e], s1 = srcs[e + 1], s2 = srcs[e + 2], s3 = srcs[e + 3];
        uint2 v0 = hs[(size_t)s0 * 16 + lane];
        uint2 v1 = hs[(size_t)s1 * 16 + lane];
        uint2 v2 = hs[(size_t)s2 * 16 + lane];
        uint2 v3 = hs[(size_t)s3 * 16 + lane];
        acc_half4(acc, v0); acc_half4(acc, v1);
        acc_half4(acc, v2); acc_half4(acc, v3);
    }
    for (; e < end; e++) acc_half4(acc, hs[(size_t)srcs[e] * 16 + lane]);

    if (c > CAP) {  // overflow fixup (empty in practice)
        int ns = min(*nspill, MAX_SPILL);
        for (int j = 0; j < ns; j++)
            if (spill_d[j] == node) acc_half4(acc, hs[(size_t)spill_s[j] * 16 + lane]);
    }

    float dd = dinv[node];
    float4 bv = reinterpret_cast<const float4*>(bias)[lane];
    float r0 = fmaf(acc.x, dd, bv.x);
    float r1 = fmaf(acc.y, dd, bv.y);
    float r2 = fmaf(acc.z, dd, bv.z);
    float r3 = fmaf(acc.w, dd, bv.w);
    if (RELU) {
        r0 = fmaxf(r0, 0.f); r1 = fmaxf(r1, 0.f);
        r2 = fmaxf(r2, 0.f); r3 = fmaxf(r3, 0.f);
    }
    out[(size_t)node * 16 + lane] = make_float4(r0, r1, r2, r3);
}

// ---------------------------------------------------------------------------
// launch: capture-graph fork — CSR build runs concurrently with GEMM1(raw)
// ---------------------------------------------------------------------------
extern "C" void kernel_launch(void* const* d_in, const int* in_sizes, int n_in,
                              void* d_out, int out_size) {
    const float* x = (const float*)d_in[0];
    const int* edge_index = (const int*)d_in[1];
    const float* W1 = (const float*)d_in[2];
    const float* b1 = (const float*)d_in[3];
    const float* W2 = (const float*)d_in[4];
    const float* b2 = (const float*)d_in[5];
    float* out = (float*)d_out;

    const int IN_CH = 256;
    const int N = in_sizes[0] / IN_CH;  // 100000
    const int E = in_sizes[1] / 2;      // 3200000
    const int* src = edge_index;
    const int* dst = edge_index + E;

    int *cnt, *srcs, *nspill, *spill_d, *spill_s;
    float *dinv, *hid;
    __half *h1, *h2;
    cudaGetSymbolAddress((void**)&cnt, g_cnt);
    cudaGetSymbolAddress((void**)&srcs, g_srcs);
    cudaGetSymbolAddress((void**)&nspill, g_nspill);
    cudaGetSymbolAddress((void**)&spill_d, g_spill_d);
    cudaGetSymbolAddress((void**)&spill_s, g_spill_s);
    cudaGetSymbolAddress((void**)&dinv, g_dinv);
    cudaGetSymbolAddress((void**)&h1, g_h1);
    cudaGetSymbolAddress((void**)&hid, g_hid);
    cudaGetSymbolAddress((void**)&h2, g_h2);

    // one-time setup on the first (uncaptured) correctness call
    static cudaStream_t s_side = nullptr;
    static cudaEvent_t evA = nullptr, evB = nullptr;
    if (s_side == nullptr) {
        cudaFuncSetAttribute((const void*)gemm_tf32_kernel<256, false>,
                             cudaFuncAttributeMaxDynamicSharedMemorySize, GEMM_SMEM_BYTES);
        cudaFuncSetAttribute((const void*)gemm_tf32_kernel<64, true>,
                             cudaFuncAttributeMaxDynamicSharedMemorySize, GEMM_SMEM_BYTES);
        cudaStreamCreateWithFlags(&s_side, cudaStreamNonBlocking);
        cudaEventCreateWithFlags(&evA, cudaEventDisableTiming);
        cudaEventCreateWithFlags(&evB, cudaEventDisableTiming);
    }

    const int T = 256;
    int nBlkN = (N + T - 1) / T;
    int nBlkE = (E + T - 1) / T;
    int nBlkG = (N + 127) / 128;
    int nBlkGa = (N * 16 + T - 1) / T;

    // main stream: zero counters, then fork
    zero_cnt_kernel<<<nBlkN, T>>>(cnt, nspill, N);
    cudaEventRecord(evA, 0);

    // side branch: CSR build + dinv
    cudaStreamWaitEvent(s_side, evA, 0);
    hist_scatter_kernel<<<nBlkE, T, 0, s_side>>>(src, dst, cnt, srcs,
                                                 nspill, spill_d, spill_s, E);
    dinv_kernel<<<nBlkN, T, 0, s_side>>>(cnt, dinv, N);
    cudaEventRecord(evB, s_side);

    // main branch: GEMM1 raw (independent of CSR/dinv) — overlaps with side
    gemm_tf32_kernel<256, false><<<nBlkG, T, GEMM_SMEM_BYTES>>>(x, W1, dinv, h1, N);

    // join, then scale h1 by dinv in place
    cudaStreamWaitEvent(0, evB, 0);
    scale_h1_kernel<<<nBlkGa, T>>>((uint2*)h1, dinv, N);

    // layer 1 aggregation (+b1, relu) -> hid fp32
    gather_kernel<true><<<nBlkGa, T>>>((const uint2*)h1, cnt, srcs, dinv, b1,
                                       nspill, spill_d, spill_s, (float4*)hid, N);

    // layer 2 GEMM (scaled) -> h2 fp16
    gemm_tf32_kernel<64, true><<<nBlkG, T, GEMM_SMEM_BYTES>>>(hid, W2, dinv, h2, N);

    // final aggregation (+b2) -> fp32 out
    gather_kernel<false><<<nBlkGa, T>>>((const uint2*)h2, cnt, srcs, dinv, b2,
                                        nspill, spill_d, spill_s, (float4*)out, N);
}